// round 1
// baseline (speedup 1.0000x reference)
#include <cuda_runtime.h>
#include <math.h>

#define NN   50000
#define EE   1600000
#define INC  128
#define HID  64
#define OUTC 16

// ---- device scratch (static; no runtime allocation allowed) ----
__device__ float g_h[NN * HID];      // lin output (aggregation input), layers 1/2
__device__ float g_h2[NN * HID];     // aggregation output (next lin input)
__device__ float g_h16[NN * OUTC];   // lin3 output
__device__ float g_asrc[NN];
__device__ float g_adst[NN];
__device__ int   g_rowptr[NN + 1];
__device__ int   g_cnt[NN];
__device__ int   g_cur[NN];
__device__ int   g_srcs[EE];         // src node per CSR slot (sorted by dst)
__device__ float g_e[EE];            // per-edge logit in CSR order

// ================= CSR build =================
__global__ void zero_cnt_kernel() {
    int i = blockIdx.x * blockDim.x + threadIdx.x;
    if (i < NN) g_cnt[i] = 0;
}

__global__ void hist_kernel(const int* __restrict__ ei) {
    int i = blockIdx.x * blockDim.x + threadIdx.x;
    if (i < EE) atomicAdd(&g_cnt[ei[EE + i]], 1);
}

// single-block exclusive scan over g_cnt -> g_rowptr (N=50000, 1024 threads)
__global__ void scan_kernel() {
    __shared__ int sm[1024];
    __shared__ int carry;
    int tid = threadIdx.x;
    if (tid == 0) carry = 0;
    __syncthreads();
    for (int base = 0; base < NN; base += 1024) {
        int idx = base + tid;
        int v = (idx < NN) ? g_cnt[idx] : 0;
        sm[tid] = v;
        __syncthreads();
        for (int off = 1; off < 1024; off <<= 1) {
            int t = (tid >= off) ? sm[tid - off] : 0;
            __syncthreads();
            sm[tid] += t;
            __syncthreads();
        }
        int incl = sm[tid];
        if (idx < NN) g_rowptr[idx] = carry + incl - v;
        __syncthreads();
        if (tid == 0) carry += sm[1023];
        __syncthreads();
    }
    if (tid == 0) g_rowptr[NN] = carry;
}

__global__ void copy_cur_kernel() {
    int i = blockIdx.x * blockDim.x + threadIdx.x;
    if (i < NN) g_cur[i] = g_rowptr[i];
}

__global__ void scatter_kernel(const int* __restrict__ ei) {
    int i = blockIdx.x * blockDim.x + threadIdx.x;
    if (i < EE) {
        int d = ei[EE + i];
        int pos = atomicAdd(&g_cur[d], 1);
        g_srcs[pos] = ei[i];
    }
}

// ================= linear: H = X @ W, plus per-node alpha_src/alpha_dst =================
// XSEL: 0 = param X, 1 = g_h2.  HSEL: 0 = g_h, 1 = g_h16.
template<int IN, int OUT, int XSEL, int HSEL>
__global__ void lin_kernel(const float* __restrict__ Xp,
                           const float* __restrict__ W,
                           const float* __restrict__ av,   // a_src
                           const float* __restrict__ adv)  // a_dst
{
    constexpr int NPB = 128 / OUT;   // nodes per block
    __shared__ float sw[IN * OUT];
    __shared__ float sx[NPB * IN];
    __shared__ float s_as[NPB], s_ad[NPB];

    const float* X = (XSEL == 0) ? Xp : g_h2;
    float* H = (HSEL == 0) ? g_h : g_h16;

    int tid = threadIdx.x;
    for (int i = tid; i < IN * OUT; i += 128) sw[i] = W[i];
    int node0 = blockIdx.x * NPB;
    for (int i = tid; i < NPB * IN; i += 128) {
        int n = node0 + i / IN;
        sx[i] = (n < NN) ? X[(size_t)n * IN + (i % IN)] : 0.f;
    }
    if (tid < NPB) { s_as[tid] = 0.f; s_ad[tid] = 0.f; }
    __syncthreads();

    int g = tid / OUT, c = tid % OUT;
    const float* xr = &sx[g * IN];
    float sum = 0.f;
#pragma unroll 8
    for (int k = 0; k < IN; k++) sum = fmaf(xr[k], sw[k * OUT + c], sum);

    int n = node0 + g;
    if (n < NN) H[(size_t)n * OUT + c] = sum;
    atomicAdd(&s_as[g], sum * av[c]);
    atomicAdd(&s_ad[g], sum * adv[c]);
    __syncthreads();
    if (tid < NPB) {
        int nn = node0 + tid;
        if (nn < NN) { g_asrc[nn] = s_as[tid]; g_adst[nn] = s_ad[tid]; }
    }
}

// ================= aggregation, C=64, warp per dst node =================
template<bool RELU>
__global__ void agg64_kernel(const float* __restrict__ b) {
    int w = (blockIdx.x * blockDim.x + threadIdx.x) >> 5;
    int lane = threadIdx.x & 31;
    if (w >= NN) return;

    int start = g_rowptr[w], end = g_rowptr[w + 1];
    float adst_d = g_adst[w];

    // pass 1: logits + max (lanes strided over edges)
    float mx = -INFINITY;
    for (int j = start + lane; j < end; j += 32) {
        int s = g_srcs[j];
        float e = g_asrc[s] + adst_d;
        e = (e > 0.f) ? e : 0.2f * e;
        g_e[j] = e;
        mx = fmaxf(mx, e);
    }
#pragma unroll
    for (int o = 16; o; o >>= 1) mx = fmaxf(mx, __shfl_xor_sync(0xffffffffu, mx, o));

    // pass 2: exp-sum + weighted feature accumulation (lane owns 2 channels)
    float psum = 0.f, ax = 0.f, ay = 0.f;
    for (int j0 = start; j0 < end; j0 += 32) {
        int j = j0 + lane;
        float p = 0.f; int s = 0;
        if (j < end) { p = __expf(g_e[j] - mx); psum += p; s = g_srcs[j]; }
        int cnt = min(32, end - j0);
        for (int k = 0; k < cnt; k++) {
            float pk = __shfl_sync(0xffffffffu, p, k);
            int   sk = __shfl_sync(0xffffffffu, s, k);
            float2 hv = *reinterpret_cast<const float2*>(&g_h[(size_t)sk * 64 + lane * 2]);
            ax = fmaf(pk, hv.x, ax);
            ay = fmaf(pk, hv.y, ay);
        }
    }
#pragma unroll
    for (int o = 16; o; o >>= 1) psum += __shfl_xor_sync(0xffffffffu, psum, o);

    float inv = 1.f / (psum + 1e-16f);
    float vx = ax * inv + b[lane * 2];
    float vy = ay * inv + b[lane * 2 + 1];
    if (RELU) { vx = fmaxf(vx, 0.f); vy = fmaxf(vy, 0.f); }
    *reinterpret_cast<float2*>(&g_h2[(size_t)w * 64 + lane * 2]) = make_float2(vx, vy);
}

// ================= aggregation, C=16, warp per dst node (2 edges/iter) =================
__global__ void agg16_kernel(const float* __restrict__ b, float* __restrict__ O) {
    int w = (blockIdx.x * blockDim.x + threadIdx.x) >> 5;
    int lane = threadIdx.x & 31;
    if (w >= NN) return;

    int start = g_rowptr[w], end = g_rowptr[w + 1];
    float adst_d = g_adst[w];

    float mx = -INFINITY;
    for (int j = start + lane; j < end; j += 32) {
        int s = g_srcs[j];
        float e = g_asrc[s] + adst_d;
        e = (e > 0.f) ? e : 0.2f * e;
        g_e[j] = e;
        mx = fmaxf(mx, e);
    }
#pragma unroll
    for (int o = 16; o; o >>= 1) mx = fmaxf(mx, __shfl_xor_sync(0xffffffffu, mx, o));

    int grp = lane >> 4, ch = lane & 15;
    float psum = 0.f, acc = 0.f;
    for (int j0 = start; j0 < end; j0 += 32) {
        int j = j0 + lane;
        float p = 0.f; int s = 0;
        if (j < end) { p = __expf(g_e[j] - mx); psum += p; s = g_srcs[j]; }
        int cnt = min(32, end - j0);
        for (int k = 0; k < cnt; k += 2) {
            int kk = k + grp;   // kk <= 31 always; lanes with j>=end carry p=0
            float pk = __shfl_sync(0xffffffffu, p, kk);
            int   sk = __shfl_sync(0xffffffffu, s, kk);
            acc = fmaf(pk, g_h16[(size_t)sk * 16 + ch], acc);
        }
    }
#pragma unroll
    for (int o = 16; o; o >>= 1) psum += __shfl_xor_sync(0xffffffffu, psum, o);
    acc += __shfl_xor_sync(0xffffffffu, acc, 16);

    if (lane < 16) {
        float v = acc / (psum + 1e-16f) + b[ch];
        O[(size_t)w * 16 + ch] = v;   // final layer: no relu
    }
}

// ================= launch =================
extern "C" void kernel_launch(void* const* d_in, const int* in_sizes, int n_in,
                              void* d_out, int out_size) {
    const float* x   = (const float*)d_in[0];
    const int*   ei  = (const int*)  d_in[1];
    // d_in[2] = edge_weight (unused by GATConv)
    const float* W1  = (const float*)d_in[3];
    const float* as1 = (const float*)d_in[4];
    const float* ad1 = (const float*)d_in[5];
    const float* b1  = (const float*)d_in[6];
    const float* W2  = (const float*)d_in[7];
    const float* as2 = (const float*)d_in[8];
    const float* ad2 = (const float*)d_in[9];
    const float* b2  = (const float*)d_in[10];
    const float* W3  = (const float*)d_in[11];
    const float* as3 = (const float*)d_in[12];
    const float* ad3 = (const float*)d_in[13];
    const float* b3  = (const float*)d_in[14];
    float* out = (float*)d_out;

    // ---- CSR build (dst-sorted; shared by all 3 layers) ----
    zero_cnt_kernel<<<(NN + 255) / 256, 256>>>();
    hist_kernel<<<(EE + 255) / 256, 256>>>(ei);
    scan_kernel<<<1, 1024>>>();
    copy_cur_kernel<<<(NN + 255) / 256, 256>>>();
    scatter_kernel<<<(EE + 255) / 256, 256>>>(ei);

    const int AGG_BLOCKS = (NN * 32 + 255) / 256;

    // layer 1: X[50000,128] @ W1 -> g_h ; aggregate -> g_h2 (relu)
    lin_kernel<128, 64, 0, 0><<<NN / 2, 128>>>(x, W1, as1, ad1);
    agg64_kernel<true><<<AGG_BLOCKS, 256>>>(b1);

    // layer 2: g_h2 @ W2 -> g_h ; aggregate -> g_h2 (relu)
    lin_kernel<64, 64, 1, 0><<<NN / 2, 128>>>(x, W2, as2, ad2);
    agg64_kernel<true><<<AGG_BLOCKS, 256>>>(b2);

    // layer 3: g_h2 @ W3 -> g_h16 ; aggregate -> d_out (no relu)
    lin_kernel<64, 16, 1, 1><<<NN / 8, 128>>>(x, W3, as3, ad3);
    agg16_kernel<<<AGG_BLOCKS, 256>>>(b3, out);
}

// round 2
// speedup vs baseline: 1.6296x; 1.6296x over previous
#include <cuda_runtime.h>
#include <math.h>

#define NN   50000
#define EE   1600000
#define INC  128
#define HID  64
#define OUTC 16

// ---- device scratch (static; no runtime allocation allowed) ----
__device__ float g_h[NN * HID];      // lin output (aggregation input), layers 1/2
__device__ float g_h2[NN * HID];     // aggregation output (next lin input)
__device__ float g_h16[NN * OUTC];   // lin3 output
__device__ float g_asrc[NN];
__device__ float g_adst[NN];
__device__ int   g_rowptr[NN + 1];
__device__ int   g_cnt[NN];
__device__ int   g_cur[NN];
__device__ int   g_srcs[EE];         // src node per CSR slot (sorted by dst)
__device__ float g_e[EE];            // per-edge logit in CSR order

// ================= CSR build =================
__global__ void zero_cnt_kernel() {
    int i = blockIdx.x * blockDim.x + threadIdx.x;
    if (i < NN) g_cnt[i] = 0;
}

__global__ void hist_kernel(const int* __restrict__ ei) {
    int i = blockIdx.x * blockDim.x + threadIdx.x;
    if (i < EE) atomicAdd(&g_cnt[ei[EE + i]], 1);
}

// single-block exclusive scan over g_cnt -> g_rowptr + g_cur
__global__ void scan_kernel() {
    __shared__ int sm[1024];
    __shared__ int carry;
    int tid = threadIdx.x;
    if (tid == 0) carry = 0;
    __syncthreads();
    for (int base = 0; base < NN; base += 1024) {
        int idx = base + tid;
        int v = (idx < NN) ? g_cnt[idx] : 0;
        sm[tid] = v;
        __syncthreads();
        for (int off = 1; off < 1024; off <<= 1) {
            int t = (tid >= off) ? sm[tid - off] : 0;
            __syncthreads();
            sm[tid] += t;
            __syncthreads();
        }
        int incl = sm[tid];
        if (idx < NN) {
            int ex = carry + incl - v;
            g_rowptr[idx] = ex;
            g_cur[idx]    = ex;
        }
        __syncthreads();
        if (tid == 0) carry += sm[1023];
        __syncthreads();
    }
    if (tid == 0) g_rowptr[NN] = carry;
}

__global__ void scatter_kernel(const int* __restrict__ ei) {
    int i = blockIdx.x * blockDim.x + threadIdx.x;
    if (i < EE) {
        int d = ei[EE + i];
        int pos = atomicAdd(&g_cur[d], 1);
        g_srcs[pos] = ei[i];
    }
}

// ================= linear: H = X @ W, plus per-node alpha_src/alpha_dst =================
// XSEL: 0 = param X, 1 = g_h2.  HSEL: 0 = g_h, 1 = g_h16.
template<int IN, int OUT, int XSEL, int HSEL>
__global__ void lin_kernel(const float* __restrict__ Xp,
                           const float* __restrict__ W,
                           const float* __restrict__ av,   // a_src
                           const float* __restrict__ adv)  // a_dst
{
    constexpr int NPB = 128 / OUT;   // nodes per block
    __shared__ float sw[IN * OUT];
    __shared__ float sx[NPB * IN];
    __shared__ float s_as[8], s_ad[8];   // per-16-lane-group partials (<=8 groups)

    const float* X = (XSEL == 0) ? Xp : g_h2;
    float* H = (HSEL == 0) ? g_h : g_h16;

    int tid = threadIdx.x;
    for (int i = tid; i < IN * OUT; i += 128) sw[i] = W[i];
    int node0 = blockIdx.x * NPB;
    for (int i = tid; i < NPB * IN; i += 128) {
        int n = node0 + i / IN;
        sx[i] = (n < NN) ? X[(size_t)n * IN + (i % IN)] : 0.f;
    }
    __syncthreads();

    int g = tid / OUT, c = tid % OUT;
    const float* xr = &sx[g * IN];
    float sum = 0.f;
#pragma unroll 8
    for (int k = 0; k < IN; k++) sum = fmaf(xr[k], sw[k * OUT + c], sum);

    int n = node0 + g;
    if (n < NN) H[(size_t)n * OUT + c] = sum;

    // reduce sum*av / sum*adv over the OUT channels of each node (shfl tree)
    float vs = sum * av[c];
    float vd = sum * adv[c];
    // channels of a node occupy OUT consecutive lanes; OUT is 64 or 16.
    // reduce within min(OUT,32)-lane segments:
#pragma unroll
    for (int off = (OUT >= 32 ? 16 : OUT / 2); off >= 1; off >>= 1) {
        vs += __shfl_xor_sync(0xffffffffu, vs, off);
        vd += __shfl_xor_sync(0xffffffffu, vd, off);
    }
    // segment leader writes its partial
    constexpr int SEG = (OUT >= 32 ? 32 : OUT);            // lanes per partial
    constexpr int SEGS_PER_NODE = OUT / SEG;               // 2 for OUT=64, 1 for OUT=16
    int seg = tid / SEG;                                   // segment index within block
    if ((tid & (SEG - 1)) == 0) { s_as[seg] = vs; s_ad[seg] = vd; }
    __syncthreads();
    if (tid < NPB) {
        int nn = node0 + tid;
        if (nn < NN) {
            float a = 0.f, d = 0.f;
#pragma unroll
            for (int u = 0; u < SEGS_PER_NODE; u++) {
                a += s_as[tid * SEGS_PER_NODE + u];
                d += s_ad[tid * SEGS_PER_NODE + u];
            }
            g_asrc[nn] = a; g_adst[nn] = d;
        }
    }
}

// ================= aggregation, C=64, warp per dst node =================
template<bool RELU>
__global__ void __launch_bounds__(256) agg64_kernel(const float* __restrict__ b) {
    int w = (blockIdx.x * blockDim.x + threadIdx.x) >> 5;
    int lane = threadIdx.x & 31;
    if (w >= NN) return;

    int start = g_rowptr[w], end = g_rowptr[w + 1];
    float adst_d = g_adst[w];

    // pass 1: logits + max (lanes strided over edges)
    float mx = -INFINITY;
    for (int j = start + lane; j < end; j += 32) {
        int s = g_srcs[j];
        float e = g_asrc[s] + adst_d;
        e = (e > 0.f) ? e : 0.2f * e;
        g_e[j] = e;
        mx = fmaxf(mx, e);
    }
#pragma unroll
    for (int o = 16; o; o >>= 1) mx = fmaxf(mx, __shfl_xor_sync(0xffffffffu, mx, o));

    // pass 2: exp-sum + weighted feature accumulation (lane owns 2 channels).
    // Inactive lanes carry p=0,s=0 -> their fma contributes exactly 0, so the
    // inner loop runs a fixed 32 iterations, unrolled in chunks of 8 for MLP.
    float psum = 0.f, ax = 0.f, ay = 0.f;
    const size_t ch2 = (size_t)(lane * 2);
    for (int j0 = start; j0 < end; j0 += 32) {
        int j = j0 + lane;
        float p = 0.f; int s = 0;
        if (j < end) { p = __expf(g_e[j] - mx); psum += p; s = g_srcs[j]; }
        int cnt = end - j0;
#pragma unroll
        for (int kb = 0; kb < 32; kb += 8) {
            if (kb < cnt) {
                float pk[8]; int sk[8];
#pragma unroll
                for (int u = 0; u < 8; u++) {
                    pk[u] = __shfl_sync(0xffffffffu, p, kb + u);
                    sk[u] = __shfl_sync(0xffffffffu, s, kb + u);
                }
                float2 hv[8];
#pragma unroll
                for (int u = 0; u < 8; u++)
                    hv[u] = *reinterpret_cast<const float2*>(&g_h[(size_t)sk[u] * 64 + ch2]);
#pragma unroll
                for (int u = 0; u < 8; u++) {
                    ax = fmaf(pk[u], hv[u].x, ax);
                    ay = fmaf(pk[u], hv[u].y, ay);
                }
            }
        }
    }
#pragma unroll
    for (int o = 16; o; o >>= 1) psum += __shfl_xor_sync(0xffffffffu, psum, o);

    float inv = 1.f / (psum + 1e-16f);
    float vx = ax * inv + b[lane * 2];
    float vy = ay * inv + b[lane * 2 + 1];
    if (RELU) { vx = fmaxf(vx, 0.f); vy = fmaxf(vy, 0.f); }
    *reinterpret_cast<float2*>(&g_h2[(size_t)w * 64 + ch2]) = make_float2(vx, vy);
}

// ================= aggregation, C=16, warp per dst node (2 edges/iter) =================
__global__ void __launch_bounds__(256) agg16_kernel(const float* __restrict__ b,
                                                    float* __restrict__ O) {
    int w = (blockIdx.x * blockDim.x + threadIdx.x) >> 5;
    int lane = threadIdx.x & 31;
    if (w >= NN) return;

    int start = g_rowptr[w], end = g_rowptr[w + 1];
    float adst_d = g_adst[w];

    float mx = -INFINITY;
    for (int j = start + lane; j < end; j += 32) {
        int s = g_srcs[j];
        float e = g_asrc[s] + adst_d;
        e = (e > 0.f) ? e : 0.2f * e;
        g_e[j] = e;
        mx = fmaxf(mx, e);
    }
#pragma unroll
    for (int o = 16; o; o >>= 1) mx = fmaxf(mx, __shfl_xor_sync(0xffffffffu, mx, o));

    int grp = lane >> 4, ch = lane & 15;
    float psum = 0.f, acc = 0.f;
    for (int j0 = start; j0 < end; j0 += 32) {
        int j = j0 + lane;
        float p = 0.f; int s = 0;
        if (j < end) { p = __expf(g_e[j] - mx); psum += p; s = g_srcs[j]; }
        int cnt = end - j0;
#pragma unroll
        for (int kb = 0; kb < 32; kb += 8) {
            if (kb < cnt) {
                // each 16-lane half handles edge kb+2u+grp; 4 edge-pairs per chunk
                float pk[4]; int sk[4];
#pragma unroll
                for (int u = 0; u < 4; u++) {
                    int kk = kb + 2 * u + grp;
                    pk[u] = __shfl_sync(0xffffffffu, p, kk);
                    sk[u] = __shfl_sync(0xffffffffu, s, kk);
                }
                float hv[4];
#pragma unroll
                for (int u = 0; u < 4; u++)
                    hv[u] = g_h16[(size_t)sk[u] * 16 + ch];
#pragma unroll
                for (int u = 0; u < 4; u++)
                    acc = fmaf(pk[u], hv[u], acc);
            }
        }
    }
#pragma unroll
    for (int o = 16; o; o >>= 1) psum += __shfl_xor_sync(0xffffffffu, psum, o);
    acc += __shfl_xor_sync(0xffffffffu, acc, 16);

    if (lane < 16) {
        float v = acc / (psum + 1e-16f) + b[ch];
        O[(size_t)w * 16 + ch] = v;   // final layer: no relu
    }
}

// ================= launch =================
extern "C" void kernel_launch(void* const* d_in, const int* in_sizes, int n_in,
                              void* d_out, int out_size) {
    const float* x   = (const float*)d_in[0];
    const int*   ei  = (const int*)  d_in[1];
    // d_in[2] = edge_weight (unused by GATConv)
    const float* W1  = (const float*)d_in[3];
    const float* as1 = (const float*)d_in[4];
    const float* ad1 = (const float*)d_in[5];
    const float* b1  = (const float*)d_in[6];
    const float* W2  = (const float*)d_in[7];
    const float* as2 = (const float*)d_in[8];
    const float* ad2 = (const float*)d_in[9];
    const float* b2  = (const float*)d_in[10];
    const float* W3  = (const float*)d_in[11];
    const float* as3 = (const float*)d_in[12];
    const float* ad3 = (const float*)d_in[13];
    const float* b3  = (const float*)d_in[14];
    float* out = (float*)d_out;

    // ---- CSR build (dst-sorted; shared by all 3 layers) ----
    zero_cnt_kernel<<<(NN + 255) / 256, 256>>>();
    hist_kernel<<<(EE + 255) / 256, 256>>>(ei);
    scan_kernel<<<1, 1024>>>();
    scatter_kernel<<<(EE + 255) / 256, 256>>>(ei);

    const int AGG_BLOCKS = (NN * 32 + 255) / 256;

    // layer 1: X[50000,128] @ W1 -> g_h ; aggregate -> g_h2 (relu)
    lin_kernel<128, 64, 0, 0><<<NN / 2, 128>>>(x, W1, as1, ad1);
    agg64_kernel<true><<<AGG_BLOCKS, 256>>>(b1);

    // layer 2: g_h2 @ W2 -> g_h ; aggregate -> g_h2 (relu)
    lin_kernel<64, 64, 1, 0><<<NN / 2, 128>>>(x, W2, as2, ad2);
    agg64_kernel<true><<<AGG_BLOCKS, 256>>>(b2);

    // layer 3: g_h2 @ W3 -> g_h16 ; aggregate -> d_out (no relu)
    lin_kernel<64, 16, 1, 1><<<NN / 8, 128>>>(x, W3, as3, ad3);
    agg16_kernel<<<AGG_BLOCKS, 256>>>(b3, out);
}

// round 4
// speedup vs baseline: 3.6803x; 2.2584x over previous
#include <cuda_runtime.h>
#include <math.h>

#define NN   50000
#define EE   1600000

// ---- device scratch ----
__device__ float g_h[NN * 64];
__device__ float g_h2[NN * 64];
__device__ float g_h16[NN * 16];
__device__ float g_asrc[NN];
__device__ float g_adst[NN];
__device__ float g_amax[3];
__device__ int   g_rowptr[NN + 1];
__device__ int   g_cnt[NN];
__device__ int   g_cur[NN];
__device__ int   g_srcs[EE];
__device__ int   g_bsum[256];

#define SCAN_B 196   // ceil(NN/256)

__device__ __forceinline__ void atomicMaxF(float* a, float v) {
    int old = __float_as_int(*a);
    while (__int_as_float(old) < v) {
        int assumed = old;
        old = atomicCAS((int*)a, assumed, __float_as_int(v));
        if (old == assumed) break;
    }
}

// ================= CSR build =================
__global__ void zero_cnt_kernel() {
    int i = blockIdx.x * blockDim.x + threadIdx.x;
    if (i < NN) g_cnt[i] = 0;
    if (i < 3)  g_amax[i] = -1e30f;
}

__global__ void hist_kernel(const int* __restrict__ ei) {
    int i = blockIdx.x * blockDim.x + threadIdx.x;
    if (i < EE) atomicAdd(&g_cnt[ei[EE + i]], 1);
}

__global__ void scan_reduce() {           // grid SCAN_B, 256 thr
    __shared__ int sm[256];
    int i = blockIdx.x * 256 + threadIdx.x;
    sm[threadIdx.x] = (i < NN) ? g_cnt[i] : 0;
    __syncthreads();
    for (int off = 128; off; off >>= 1) {
        if (threadIdx.x < off) sm[threadIdx.x] += sm[threadIdx.x + off];
        __syncthreads();
    }
    if (threadIdx.x == 0) g_bsum[blockIdx.x] = sm[0];
}

__global__ void scan_bsums() {            // 1 block, 256 thr
    __shared__ int sm[256];
    int tid = threadIdx.x;
    int v = (tid < SCAN_B) ? g_bsum[tid] : 0;
    sm[tid] = v;
    __syncthreads();
    for (int off = 1; off < 256; off <<= 1) {
        int t = (tid >= off) ? sm[tid - off] : 0;
        __syncthreads();
        sm[tid] += t;
        __syncthreads();
    }
    if (tid < SCAN_B) g_bsum[tid] = sm[tid] - v;         // exclusive
    if (tid == SCAN_B - 1) g_rowptr[NN] = sm[tid];       // total
}

__global__ void scan_final() {            // grid SCAN_B, 256 thr
    __shared__ int sm[256];
    int tid = threadIdx.x;
    int i = blockIdx.x * 256 + tid;
    int v = (i < NN) ? g_cnt[i] : 0;
    sm[tid] = v;
    __syncthreads();
    for (int off = 1; off < 256; off <<= 1) {
        int t = (tid >= off) ? sm[tid - off] : 0;
        __syncthreads();
        sm[tid] += t;
        __syncthreads();
    }
    if (i < NN) {
        int ex = g_bsum[blockIdx.x] + sm[tid] - v;
        g_rowptr[i] = ex;
        g_cur[i]    = ex;
    }
}

__global__ void scatter_kernel(const int* __restrict__ ei) {
    int i = blockIdx.x * blockDim.x + threadIdx.x;
    if (i < EE) {
        int d = ei[EE + i];
        int pos = atomicAdd(&g_cur[d], 1);
        g_srcs[pos] = ei[i];
    }
}

// ================= linear: H = X @ W + alpha_src/alpha_dst + global asrc max =================
__device__ __forceinline__ float compo(float4 v, int u) {
    return u == 0 ? v.x : u == 1 ? v.y : u == 2 ? v.z : v.w;
}

// XSEL: 0 = param X, 1 = g_h2.  HSEL: 0 = g_h, 1 = g_h16.
template<int IN, int OUT, int NPT, int XSEL, int HSEL, int LAYER>
__global__ void __launch_bounds__(256) lin_kernel(const float* __restrict__ Xp,
                                                  const float* __restrict__ W,
                                                  const float* __restrict__ av,
                                                  const float* __restrict__ adv)
{
    constexpr int TPG    = OUT / 4;        // threads covering one node's channels
    constexpr int GROUPS = 256 / TPG;
    constexpr int NPB    = GROUPS * NPT;   // nodes per block
    __shared__ float4 sw4[IN * OUT / 4];
    __shared__ float4 sx4[NPB * IN / 4];

    const float* X = (XSEL == 0) ? Xp : g_h2;
    float* H = (HSEL == 0) ? g_h : g_h16;
    const float4* X4 = reinterpret_cast<const float4*>(X);
    const float4* W4 = reinterpret_cast<const float4*>(W);

    int tid = threadIdx.x;
    int node0 = blockIdx.x * NPB;

    for (int i = tid; i < IN * OUT / 4; i += 256) sw4[i] = W4[i];
    for (int i = tid; i < NPB * IN / 4; i += 256) {
        int n = node0 + i / (IN / 4);
        sx4[i] = (n < NN) ? X4[(size_t)n * (IN / 4) + (i % (IN / 4))]
                          : make_float4(0.f, 0.f, 0.f, 0.f);
    }
    __syncthreads();

    int grp = tid / TPG;
    int c4  = (tid % TPG) * 4;

    float acc[NPT][4];
#pragma unroll
    for (int n = 0; n < NPT; n++)
#pragma unroll
        for (int c = 0; c < 4; c++) acc[n][c] = 0.f;

#pragma unroll 4
    for (int k4 = 0; k4 < IN / 4; k4++) {
        float4 xv[NPT];
#pragma unroll
        for (int n = 0; n < NPT; n++)
            xv[n] = sx4[(grp * NPT + n) * (IN / 4) + k4];
#pragma unroll
        for (int u = 0; u < 4; u++) {
            float4 wv = sw4[(k4 * 4 + u) * (OUT / 4) + (c4 >> 2)];
#pragma unroll
            for (int n = 0; n < NPT; n++) {
                float xk = compo(xv[n], u);
                acc[n][0] = fmaf(xk, wv.x, acc[n][0]);
                acc[n][1] = fmaf(xk, wv.y, acc[n][1]);
                acc[n][2] = fmaf(xk, wv.z, acc[n][2]);
                acc[n][3] = fmaf(xk, wv.w, acc[n][3]);
            }
        }
    }

    float4 avv  = *reinterpret_cast<const float4*>(&av[c4]);
    float4 advv = *reinterpret_cast<const float4*>(&adv[c4]);

    float local_mx = -1e30f;
#pragma unroll
    for (int n = 0; n < NPT; n++) {
        int node = node0 + grp * NPT + n;
        if (node < NN)
            *reinterpret_cast<float4*>(&H[(size_t)node * OUT + c4]) =
                make_float4(acc[n][0], acc[n][1], acc[n][2], acc[n][3]);

        float vs = acc[n][0] * avv.x + acc[n][1] * avv.y + acc[n][2] * avv.z + acc[n][3] * avv.w;
        float vd = acc[n][0] * advv.x + acc[n][1] * advv.y + acc[n][2] * advv.z + acc[n][3] * advv.w;
#pragma unroll
        for (int off = TPG / 2; off >= 1; off >>= 1) {
            vs += __shfl_xor_sync(0xffffffffu, vs, off);
            vd += __shfl_xor_sync(0xffffffffu, vd, off);
        }
        if ((tid % TPG) == 0 && node < NN) {
            g_asrc[node] = vs;
            g_adst[node] = vd;
            local_mx = fmaxf(local_mx, vs);
        }
    }
    // warp max of asrc -> global
#pragma unroll
    for (int off = 16; off >= 1; off >>= 1)
        local_mx = fmaxf(local_mx, __shfl_xor_sync(0xffffffffu, local_mx, off));
    if ((tid & 31) == 0) atomicMaxF(&g_amax[LAYER], local_mx);
}

// ================= single-pass aggregation, C=64, warp per dst node =================
// reads g_h, writes g_h2 (device globals accessed directly — NOT via params)
template<bool RELU, int LAYER>
__global__ void __launch_bounds__(256) agg64_kernel(const float* __restrict__ b)
{
    __shared__ float2 stage[8][32];
    int w = (blockIdx.x * blockDim.x + threadIdx.x) >> 5;
    int lane = threadIdx.x & 31;
    int wwarp = threadIdx.x >> 5;
    if (w >= NN) return;

    int start = g_rowptr[w], end = g_rowptr[w + 1];
    float adst = g_adst[w];
    float C = fmaxf(adst + g_amax[LAYER], 0.f);   // any per-dst shift >= max(e) works

    float psum = 0.f, ax = 0.f, ay = 0.f;
    const size_t ch2 = (size_t)(lane * 2);

    for (int j0 = start; j0 < end; j0 += 32) {
        int j = j0 + lane;
        float p = 0.f; int s = 0;
        if (j < end) {
            s = g_srcs[j];
            float t = g_asrc[s] + adst;
            float e = (t > 0.f) ? t : 0.2f * t;
            p = __expf(e - C);
            psum += p;
        }
        stage[wwarp][lane] = make_float2(p, __int_as_float(s));
        __syncwarp();
        int cnt = end - j0;
#pragma unroll
        for (int kb = 0; kb < 32; kb += 8) {
            if (kb < cnt) {
                float2 ps[8];
#pragma unroll
                for (int u = 0; u < 8; u++) ps[u] = stage[wwarp][kb + u];
                float2 hv[8];
#pragma unroll
                for (int u = 0; u < 8; u++)
                    hv[u] = *reinterpret_cast<const float2*>(
                        &g_h[(size_t)__float_as_int(ps[u].y) * 64 + ch2]);
#pragma unroll
                for (int u = 0; u < 8; u++) {
                    ax = fmaf(ps[u].x, hv[u].x, ax);
                    ay = fmaf(ps[u].x, hv[u].y, ay);
                }
            }
        }
        __syncwarp();
    }
#pragma unroll
    for (int o = 16; o; o >>= 1) psum += __shfl_xor_sync(0xffffffffu, psum, o);

    float inv = 1.f / (psum + 1e-16f);
    float vx = ax * inv + b[lane * 2];
    float vy = ay * inv + b[lane * 2 + 1];
    if (RELU) { vx = fmaxf(vx, 0.f); vy = fmaxf(vy, 0.f); }
    *reinterpret_cast<float2*>(&g_h2[(size_t)w * 64 + ch2]) = make_float2(vx, vy);
}

// ================= single-pass aggregation, C=16 =================
__global__ void __launch_bounds__(256) agg16_kernel(const float* __restrict__ b,
                                                    float* __restrict__ O)
{
    __shared__ float2 stage[8][32];
    int w = (blockIdx.x * blockDim.x + threadIdx.x) >> 5;
    int lane = threadIdx.x & 31;
    int wwarp = threadIdx.x >> 5;
    if (w >= NN) return;

    int start = g_rowptr[w], end = g_rowptr[w + 1];
    float adst = g_adst[w];
    float C = fmaxf(adst + g_amax[2], 0.f);

    int grp = lane >> 4, ch = lane & 15;
    float psum = 0.f, acc = 0.f;

    for (int j0 = start; j0 < end; j0 += 32) {
        int j = j0 + lane;
        float p = 0.f; int s = 0;
        if (j < end) {
            s = g_srcs[j];
            float t = g_asrc[s] + adst;
            float e = (t > 0.f) ? t : 0.2f * t;
            p = __expf(e - C);
            psum += p;
        }
        stage[wwarp][lane] = make_float2(p, __int_as_float(s));
        __syncwarp();
        int cnt = end - j0;
#pragma unroll
        for (int kb = 0; kb < 32; kb += 8) {
            if (kb < cnt) {
                float2 ps[4];
#pragma unroll
                for (int u = 0; u < 4; u++) ps[u] = stage[wwarp][kb + 2 * u + grp];
                float hv[4];
#pragma unroll
                for (int u = 0; u < 4; u++)
                    hv[u] = g_h16[(size_t)__float_as_int(ps[u].y) * 16 + ch];
#pragma unroll
                for (int u = 0; u < 4; u++)
                    acc = fmaf(ps[u].x, hv[u], acc);
            }
        }
        __syncwarp();
    }
#pragma unroll
    for (int o = 16; o; o >>= 1) psum += __shfl_xor_sync(0xffffffffu, psum, o);
    acc += __shfl_xor_sync(0xffffffffu, acc, 16);

    if (lane < 16) {
        O[(size_t)w * 16 + ch] = acc / (psum + 1e-16f) + b[ch];
    }
}

// ================= launch =================
extern "C" void kernel_launch(void* const* d_in, const int* in_sizes, int n_in,
                              void* d_out, int out_size) {
    const float* x   = (const float*)d_in[0];
    const int*   ei  = (const int*)  d_in[1];
    const float* W1  = (const float*)d_in[3];
    const float* as1 = (const float*)d_in[4];
    const float* ad1 = (const float*)d_in[5];
    const float* b1  = (const float*)d_in[6];
    const float* W2  = (const float*)d_in[7];
    const float* as2 = (const float*)d_in[8];
    const float* ad2 = (const float*)d_in[9];
    const float* b2  = (const float*)d_in[10];
    const float* W3  = (const float*)d_in[11];
    const float* as3 = (const float*)d_in[12];
    const float* ad3 = (const float*)d_in[13];
    const float* b3  = (const float*)d_in[14];
    float* out = (float*)d_out;

    // ---- CSR build ----
    zero_cnt_kernel<<<(NN + 255) / 256, 256>>>();
    hist_kernel<<<(EE + 255) / 256, 256>>>(ei);
    scan_reduce<<<SCAN_B, 256>>>();
    scan_bsums<<<1, 256>>>();
    scan_final<<<SCAN_B, 256>>>();
    scatter_kernel<<<(EE + 255) / 256, 256>>>(ei);

    const int AGG_GRID = (NN + 7) / 8;

    // layer 1: 32 nodes/block (smem 48KB)
    lin_kernel<128, 64, 2, 0, 0, 0><<<(NN + 31) / 32, 256>>>(x, W1, as1, ad1);
    agg64_kernel<true, 0><<<AGG_GRID, 256>>>(b1);

    // layer 2: 64 nodes/block
    lin_kernel<64, 64, 4, 1, 0, 1><<<(NN + 63) / 64, 256>>>(x, W2, as2, ad2);
    agg64_kernel<true, 1><<<AGG_GRID, 256>>>(b2);

    // layer 3: 128 nodes/block
    lin_kernel<64, 16, 2, 1, 1, 2><<<(NN + 127) / 128, 256>>>(x, W3, as3, ad3);
    agg16_kernel<<<AGG_GRID, 256>>>(b3, out);
}

// round 5
// speedup vs baseline: 3.7137x; 1.0091x over previous
#include <cuda_runtime.h>
#include <math.h>

#define NN   50000
#define EE   1600000

// ---- device scratch ----
__device__ float g_h[NN * 64];
__device__ float g_h2[NN * 64];
__device__ float g_h16[NN * 16];
__device__ float g_asrc[NN];
__device__ float g_adst[NN];
__device__ float g_amax[3];          // monotone (atomicMax only) — any M >= true max is a valid shift
__device__ int   g_rowptr[NN + 1];
__device__ int   g_cnt[NN];
__device__ int   g_cur[NN];
__device__ unsigned short g_srcs16[EE];
__device__ int   g_bsum[256];

#define SCAN_B 196   // ceil(NN/256)

__device__ __forceinline__ void atomicMaxF(float* a, float v) {
    int old = __float_as_int(*a);
    while (__int_as_float(old) < v) {
        int assumed = old;
        old = atomicCAS((int*)a, assumed, __float_as_int(v));
        if (old == assumed) break;
    }
}

// ================= CSR build =================
__global__ void zero_cnt_kernel() {
    int i = blockIdx.x * blockDim.x + threadIdx.x;
    if (i < NN) g_cnt[i] = 0;
}

__global__ void hist_kernel(const int* __restrict__ ei) {
    int i = blockIdx.x * blockDim.x + threadIdx.x;
    if (i < EE / 4) {
        int4 d = reinterpret_cast<const int4*>(ei + EE)[i];
        atomicAdd(&g_cnt[d.x], 1);
        atomicAdd(&g_cnt[d.y], 1);
        atomicAdd(&g_cnt[d.z], 1);
        atomicAdd(&g_cnt[d.w], 1);
    }
}

__global__ void scan_reduce() {           // grid SCAN_B, 256 thr
    __shared__ int sm[256];
    int i = blockIdx.x * 256 + threadIdx.x;
    sm[threadIdx.x] = (i < NN) ? g_cnt[i] : 0;
    __syncthreads();
    for (int off = 128; off; off >>= 1) {
        if (threadIdx.x < off) sm[threadIdx.x] += sm[threadIdx.x + off];
        __syncthreads();
    }
    if (threadIdx.x == 0) g_bsum[blockIdx.x] = sm[0];
}

__global__ void scan_bsums() {            // 1 block, 256 thr
    __shared__ int sm[256];
    int tid = threadIdx.x;
    int v = (tid < SCAN_B) ? g_bsum[tid] : 0;
    sm[tid] = v;
    __syncthreads();
    for (int off = 1; off < 256; off <<= 1) {
        int t = (tid >= off) ? sm[tid - off] : 0;
        __syncthreads();
        sm[tid] += t;
        __syncthreads();
    }
    if (tid < SCAN_B) g_bsum[tid] = sm[tid] - v;         // exclusive
    if (tid == SCAN_B - 1) g_rowptr[NN] = sm[tid];       // total
}

__global__ void scan_final() {            // grid SCAN_B, 256 thr
    __shared__ int sm[256];
    int tid = threadIdx.x;
    int i = blockIdx.x * 256 + tid;
    int v = (i < NN) ? g_cnt[i] : 0;
    sm[tid] = v;
    __syncthreads();
    for (int off = 1; off < 256; off <<= 1) {
        int t = (tid >= off) ? sm[tid - off] : 0;
        __syncthreads();
        sm[tid] += t;
        __syncthreads();
    }
    if (i < NN) {
        int ex = g_bsum[blockIdx.x] + sm[tid] - v;
        g_rowptr[i] = ex;
        g_cur[i]    = ex;
    }
}

__global__ void scatter_kernel(const int* __restrict__ ei) {
    int i = blockIdx.x * blockDim.x + threadIdx.x;
    if (i < EE / 4) {
        int4 s4 = reinterpret_cast<const int4*>(ei)[i];
        int4 d4 = reinterpret_cast<const int4*>(ei + EE)[i];
        int p0 = atomicAdd(&g_cur[d4.x], 1);
        int p1 = atomicAdd(&g_cur[d4.y], 1);
        int p2 = atomicAdd(&g_cur[d4.z], 1);
        int p3 = atomicAdd(&g_cur[d4.w], 1);
        g_srcs16[p0] = (unsigned short)s4.x;
        g_srcs16[p1] = (unsigned short)s4.y;
        g_srcs16[p2] = (unsigned short)s4.z;
        g_srcs16[p3] = (unsigned short)s4.w;
    }
}

// ================= linear: H = X @ W + alpha_src/alpha_dst + global asrc max =================
__device__ __forceinline__ float compo(float4 v, int u) {
    return u == 0 ? v.x : u == 1 ? v.y : u == 2 ? v.z : v.w;
}

// XSEL: 0 = param X, 1 = g_h2.  HSEL: 0 = g_h, 1 = g_h16.
template<int IN, int OUT, int NPT, int XSEL, int HSEL, int LAYER>
__global__ void __launch_bounds__(256) lin_kernel(const float* __restrict__ Xp,
                                                  const float* __restrict__ W,
                                                  const float* __restrict__ av,
                                                  const float* __restrict__ adv)
{
    constexpr int TPG    = OUT / 4;        // threads covering one node's channels
    constexpr int GROUPS = 256 / TPG;
    constexpr int NPB    = GROUPS * NPT;   // nodes per block
    __shared__ float4 sw4[IN * OUT / 4];
    __shared__ float4 sx4[NPB * IN / 4];

    const float* X = (XSEL == 0) ? Xp : g_h2;
    float* H = (HSEL == 0) ? g_h : g_h16;
    const float4* X4 = reinterpret_cast<const float4*>(X);
    const float4* W4 = reinterpret_cast<const float4*>(W);

    int tid = threadIdx.x;
    int node0 = blockIdx.x * NPB;

    for (int i = tid; i < IN * OUT / 4; i += 256) sw4[i] = W4[i];
    for (int i = tid; i < NPB * IN / 4; i += 256) {
        int n = node0 + i / (IN / 4);
        sx4[i] = (n < NN) ? X4[(size_t)n * (IN / 4) + (i % (IN / 4))]
                          : make_float4(0.f, 0.f, 0.f, 0.f);
    }
    __syncthreads();

    int grp = tid / TPG;
    int c4  = (tid % TPG) * 4;

    float acc[NPT][4];
#pragma unroll
    for (int n = 0; n < NPT; n++)
#pragma unroll
        for (int c = 0; c < 4; c++) acc[n][c] = 0.f;

#pragma unroll 4
    for (int k4 = 0; k4 < IN / 4; k4++) {
        float4 xv[NPT];
#pragma unroll
        for (int n = 0; n < NPT; n++)
            xv[n] = sx4[(grp * NPT + n) * (IN / 4) + k4];
#pragma unroll
        for (int u = 0; u < 4; u++) {
            float4 wv = sw4[(k4 * 4 + u) * (OUT / 4) + (c4 >> 2)];
#pragma unroll
            for (int n = 0; n < NPT; n++) {
                float xk = compo(xv[n], u);
                acc[n][0] = fmaf(xk, wv.x, acc[n][0]);
                acc[n][1] = fmaf(xk, wv.y, acc[n][1]);
                acc[n][2] = fmaf(xk, wv.z, acc[n][2]);
                acc[n][3] = fmaf(xk, wv.w, acc[n][3]);
            }
        }
    }

    float4 avv  = *reinterpret_cast<const float4*>(&av[c4]);
    float4 advv = *reinterpret_cast<const float4*>(&adv[c4]);

    float local_mx = -1e30f;
#pragma unroll
    for (int n = 0; n < NPT; n++) {
        int node = node0 + grp * NPT + n;
        if (node < NN)
            *reinterpret_cast<float4*>(&H[(size_t)node * OUT + c4]) =
                make_float4(acc[n][0], acc[n][1], acc[n][2], acc[n][3]);

        float vs = acc[n][0] * avv.x + acc[n][1] * avv.y + acc[n][2] * avv.z + acc[n][3] * avv.w;
        float vd = acc[n][0] * advv.x + acc[n][1] * advv.y + acc[n][2] * advv.z + acc[n][3] * advv.w;
#pragma unroll
        for (int off = TPG / 2; off >= 1; off >>= 1) {
            vs += __shfl_xor_sync(0xffffffffu, vs, off);
            vd += __shfl_xor_sync(0xffffffffu, vd, off);
        }
        if ((tid % TPG) == 0 && node < NN) {
            g_asrc[node] = vs;
            g_adst[node] = vd;
            local_mx = fmaxf(local_mx, vs);
        }
    }
#pragma unroll
    for (int off = 16; off >= 1; off >>= 1)
        local_mx = fmaxf(local_mx, __shfl_xor_sync(0xffffffffu, local_mx, off));
    if ((tid & 31) == 0) atomicMaxF(&g_amax[LAYER], local_mx);
}

// ================= single-pass aggregation, C=64, warp per dst node =================
// half-warp per edge, lane owns a float4 channel quad; reads g_h, writes g_h2
template<bool RELU, int LAYER>
__global__ void __launch_bounds__(256) agg64_kernel(const float* __restrict__ b)
{
    __shared__ float2 stage[8][32];
    int w = (blockIdx.x * blockDim.x + threadIdx.x) >> 5;
    int lane = threadIdx.x & 31;
    int wwarp = threadIdx.x >> 5;
    if (w >= NN) return;

    int start = g_rowptr[w], end = g_rowptr[w + 1];
    float adst = g_adst[w];
    float C = fmaxf(adst + g_amax[LAYER], 0.f);   // any shift >= max(e) works (uniform scale cancels)

    int grp = lane >> 4;          // which edge of a pair
    int ch4 = (lane & 15) * 4;    // channel quad
    float psum = 0.f;
    float ac0 = 0.f, ac1 = 0.f, ac2 = 0.f, ac3 = 0.f;

    for (int j0 = start; j0 < end; j0 += 32) {
        int j = j0 + lane;
        float p = 0.f; int s = 0;
        if (j < end) {
            s = (int)g_srcs16[j];
            float t = g_asrc[s] + adst;
            float e = (t > 0.f) ? t : 0.2f * t;
            p = __expf(e - C);
            psum += p;
        }
        stage[wwarp][lane] = make_float2(p, __int_as_float(s));
        __syncwarp();
        int cnt = end - j0;
#pragma unroll
        for (int kb = 0; kb < 32; kb += 8) {
            if (kb < cnt) {
                float2 ps[4];
#pragma unroll
                for (int u = 0; u < 4; u++) ps[u] = stage[wwarp][kb + 2 * u + grp];
                float4 hv[4];
#pragma unroll
                for (int u = 0; u < 4; u++)
                    hv[u] = *reinterpret_cast<const float4*>(
                        &g_h[(size_t)__float_as_int(ps[u].y) * 64 + ch4]);
#pragma unroll
                for (int u = 0; u < 4; u++) {
                    ac0 = fmaf(ps[u].x, hv[u].x, ac0);
                    ac1 = fmaf(ps[u].x, hv[u].y, ac1);
                    ac2 = fmaf(ps[u].x, hv[u].z, ac2);
                    ac3 = fmaf(ps[u].x, hv[u].w, ac3);
                }
            }
        }
        __syncwarp();
    }
#pragma unroll
    for (int o = 16; o; o >>= 1) psum += __shfl_xor_sync(0xffffffffu, psum, o);
    // combine the two edge-halves (channel quads identical across halves)
    ac0 += __shfl_xor_sync(0xffffffffu, ac0, 16);
    ac1 += __shfl_xor_sync(0xffffffffu, ac1, 16);
    ac2 += __shfl_xor_sync(0xffffffffu, ac2, 16);
    ac3 += __shfl_xor_sync(0xffffffffu, ac3, 16);

    if (lane < 16) {
        float inv = 1.f / (psum + 1e-16f);
        float4 bb = *reinterpret_cast<const float4*>(&b[ch4]);
        float v0 = ac0 * inv + bb.x;
        float v1 = ac1 * inv + bb.y;
        float v2 = ac2 * inv + bb.z;
        float v3 = ac3 * inv + bb.w;
        if (RELU) {
            v0 = fmaxf(v0, 0.f); v1 = fmaxf(v1, 0.f);
            v2 = fmaxf(v2, 0.f); v3 = fmaxf(v3, 0.f);
        }
        *reinterpret_cast<float4*>(&g_h2[(size_t)w * 64 + ch4]) =
            make_float4(v0, v1, v2, v3);
    }
}

// ================= single-pass aggregation, C=16, 8 edges/step =================
__global__ void __launch_bounds__(256) agg16_kernel(const float* __restrict__ b,
                                                    float* __restrict__ O)
{
    __shared__ float2 stage[8][32];
    int w = (blockIdx.x * blockDim.x + threadIdx.x) >> 5;
    int lane = threadIdx.x & 31;
    int wwarp = threadIdx.x >> 5;
    if (w >= NN) return;

    int start = g_rowptr[w], end = g_rowptr[w + 1];
    float adst = g_adst[w];
    float C = fmaxf(adst + g_amax[2], 0.f);

    int grp = lane >> 2;        // which of 8 edges
    int ch4 = (lane & 3) * 4;   // channel quad (16 channels = 4 quads)
    float psum = 0.f;
    float ac0 = 0.f, ac1 = 0.f, ac2 = 0.f, ac3 = 0.f;

    for (int j0 = start; j0 < end; j0 += 32) {
        int j = j0 + lane;
        float p = 0.f; int s = 0;
        if (j < end) {
            s = (int)g_srcs16[j];
            float t = g_asrc[s] + adst;
            float e = (t > 0.f) ? t : 0.2f * t;
            p = __expf(e - C);
            psum += p;
        }
        stage[wwarp][lane] = make_float2(p, __int_as_float(s));
        __syncwarp();
        int cnt = end - j0;
#pragma unroll
        for (int kb = 0; kb < 32; kb += 8) {
            if (kb < cnt) {
                float2 ps = stage[wwarp][kb + grp];
                float4 hv = *reinterpret_cast<const float4*>(
                    &g_h16[(size_t)__float_as_int(ps.y) * 16 + ch4]);
                ac0 = fmaf(ps.x, hv.x, ac0);
                ac1 = fmaf(ps.x, hv.y, ac1);
                ac2 = fmaf(ps.x, hv.z, ac2);
                ac3 = fmaf(ps.x, hv.w, ac3);
            }
        }
        __syncwarp();
    }
#pragma unroll
    for (int o = 16; o; o >>= 1) psum += __shfl_xor_sync(0xffffffffu, psum, o);
    // reduce across the 8 edge-groups (grp = lane bits 2..4)
#pragma unroll
    for (int o = 4; o <= 16; o <<= 1) {
        ac0 += __shfl_xor_sync(0xffffffffu, ac0, o);
        ac1 += __shfl_xor_sync(0xffffffffu, ac1, o);
        ac2 += __shfl_xor_sync(0xffffffffu, ac2, o);
        ac3 += __shfl_xor_sync(0xffffffffu, ac3, o);
    }

    if (lane < 4) {
        float inv = 1.f / (psum + 1e-16f);
        float4 bb = *reinterpret_cast<const float4*>(&b[ch4]);
        *reinterpret_cast<float4*>(&O[(size_t)w * 16 + ch4]) =
            make_float4(ac0 * inv + bb.x, ac1 * inv + bb.y,
                        ac2 * inv + bb.z, ac3 * inv + bb.w);
    }
}

// ================= launch =================
static cudaStream_t g_s2 = 0;
static cudaEvent_t  g_eF = 0, g_eJ = 0;

extern "C" void kernel_launch(void* const* d_in, const int* in_sizes, int n_in,
                              void* d_out, int out_size) {
    const float* x   = (const float*)d_in[0];
    const int*   ei  = (const int*)  d_in[1];
    const float* W1  = (const float*)d_in[3];
    const float* as1 = (const float*)d_in[4];
    const float* ad1 = (const float*)d_in[5];
    const float* b1  = (const float*)d_in[6];
    const float* W2  = (const float*)d_in[7];
    const float* as2 = (const float*)d_in[8];
    const float* ad2 = (const float*)d_in[9];
    const float* b2  = (const float*)d_in[10];
    const float* W3  = (const float*)d_in[11];
    const float* as3 = (const float*)d_in[12];
    const float* ad3 = (const float*)d_in[13];
    const float* b3  = (const float*)d_in[14];
    float* out = (float*)d_out;

    // lazy one-time host resources (created on the uncaptured correctness call;
    // identical device work enqueued on every call)
    if (!g_s2) {
        cudaStreamCreateWithFlags(&g_s2, cudaStreamNonBlocking);
        cudaEventCreateWithFlags(&g_eF, cudaEventDisableTiming);
        cudaEventCreateWithFlags(&g_eJ, cudaEventDisableTiming);
    }

    // ---- fork: lin1 on side stream, CSR build on main stream ----
    cudaEventRecord(g_eF, 0);
    cudaStreamWaitEvent(g_s2, g_eF, 0);
    lin_kernel<128, 64, 2, 0, 0, 0><<<(NN + 31) / 32, 256, 0, g_s2>>>(x, W1, as1, ad1);
    cudaEventRecord(g_eJ, g_s2);

    zero_cnt_kernel<<<(NN + 255) / 256, 256>>>();
    hist_kernel<<<(EE / 4 + 255) / 256, 256>>>(ei);
    scan_reduce<<<SCAN_B, 256>>>();
    scan_bsums<<<1, 256>>>();
    scan_final<<<SCAN_B, 256>>>();
    scatter_kernel<<<(EE / 4 + 255) / 256, 256>>>(ei);

    cudaStreamWaitEvent(0, g_eJ, 0);   // join lin1 into main stream

    const int AGG_GRID = (NN + 7) / 8;

    agg64_kernel<true, 0><<<AGG_GRID, 256>>>(b1);

    lin_kernel<64, 64, 4, 1, 0, 1><<<(NN + 63) / 64, 256>>>(x, W2, as2, ad2);
    agg64_kernel<true, 1><<<AGG_GRID, 256>>>(b2);

    lin_kernel<64, 16, 2, 1, 1, 2><<<(NN + 127) / 128, 256>>>(x, W3, as3, ad3);
    agg16_kernel<<<AGG_GRID, 256>>>(b3, out);
}

// round 6
// speedup vs baseline: 4.0610x; 1.0935x over previous
#include <cuda_runtime.h>
#include <cuda_fp16.h>
#include <math.h>

#define NN   50000
#define EE   1600000

// ---- device scratch ----
__device__ uint4 g_hh4[NN * 8];      // h for layers 1/2 in fp16: 64 half = 128B/node
__device__ float g_h2[NN * 64];      // aggregation output (fp32, next lin input)
__device__ float g_h16[NN * 16];     // lin3 output (fp32)
__device__ float g_asrc[NN];
__device__ float g_adst[NN];
__device__ float g_amax[3];          // monotone (atomicMax only) — any M >= true max is a valid shift
__device__ int   g_rowptr[NN + 1];
__device__ int   g_cnt[NN];
__device__ int   g_cur[NN];
__device__ unsigned short g_srcs16[EE];
__device__ int   g_bsum[256];

#define SCAN_B 196   // ceil(NN/256)

__device__ __forceinline__ void atomicMaxF(float* a, float v) {
    int old = __float_as_int(*a);
    while (__int_as_float(old) < v) {
        int assumed = old;
        old = atomicCAS((int*)a, assumed, __float_as_int(v));
        if (old == assumed) break;
    }
}

// ================= CSR build =================
__global__ void zero_cnt_kernel() {
    int i = blockIdx.x * blockDim.x + threadIdx.x;
    if (i < NN) g_cnt[i] = 0;
}

__global__ void hist_kernel(const int* __restrict__ ei) {
    int i = blockIdx.x * blockDim.x + threadIdx.x;
    if (i < EE / 4) {
        int4 d = reinterpret_cast<const int4*>(ei + EE)[i];
        atomicAdd(&g_cnt[d.x], 1);
        atomicAdd(&g_cnt[d.y], 1);
        atomicAdd(&g_cnt[d.z], 1);
        atomicAdd(&g_cnt[d.w], 1);
    }
}

__global__ void scan_reduce() {           // grid SCAN_B, 256 thr
    __shared__ int sm[256];
    int i = blockIdx.x * 256 + threadIdx.x;
    sm[threadIdx.x] = (i < NN) ? g_cnt[i] : 0;
    __syncthreads();
    for (int off = 128; off; off >>= 1) {
        if (threadIdx.x < off) sm[threadIdx.x] += sm[threadIdx.x + off];
        __syncthreads();
    }
    if (threadIdx.x == 0) g_bsum[blockIdx.x] = sm[0];
}

__global__ void scan_bsums() {            // 1 block, 256 thr
    __shared__ int sm[256];
    int tid = threadIdx.x;
    int v = (tid < SCAN_B) ? g_bsum[tid] : 0;
    sm[tid] = v;
    __syncthreads();
    for (int off = 1; off < 256; off <<= 1) {
        int t = (tid >= off) ? sm[tid - off] : 0;
        __syncthreads();
        sm[tid] += t;
        __syncthreads();
    }
    if (tid < SCAN_B) g_bsum[tid] = sm[tid] - v;         // exclusive
    if (tid == SCAN_B - 1) g_rowptr[NN] = sm[tid];       // total
}

__global__ void scan_final() {            // grid SCAN_B, 256 thr
    __shared__ int sm[256];
    int tid = threadIdx.x;
    int i = blockIdx.x * 256 + tid;
    int v = (i < NN) ? g_cnt[i] : 0;
    sm[tid] = v;
    __syncthreads();
    for (int off = 1; off < 256; off <<= 1) {
        int t = (tid >= off) ? sm[tid - off] : 0;
        __syncthreads();
        sm[tid] += t;
        __syncthreads();
    }
    if (i < NN) {
        int ex = g_bsum[blockIdx.x] + sm[tid] - v;
        g_rowptr[i] = ex;
        g_cur[i]    = ex;
    }
}

__global__ void scatter_kernel(const int* __restrict__ ei) {
    int i = blockIdx.x * blockDim.x + threadIdx.x;
    if (i < EE / 4) {
        int4 s4 = reinterpret_cast<const int4*>(ei)[i];
        int4 d4 = reinterpret_cast<const int4*>(ei + EE)[i];
        int p0 = atomicAdd(&g_cur[d4.x], 1);
        int p1 = atomicAdd(&g_cur[d4.y], 1);
        int p2 = atomicAdd(&g_cur[d4.z], 1);
        int p3 = atomicAdd(&g_cur[d4.w], 1);
        g_srcs16[p0] = (unsigned short)s4.x;
        g_srcs16[p1] = (unsigned short)s4.y;
        g_srcs16[p2] = (unsigned short)s4.z;
        g_srcs16[p3] = (unsigned short)s4.w;
    }
}

// ================= linear: H = X @ W + alpha_src/alpha_dst + global asrc max =================
__device__ __forceinline__ float compo(float4 v, int u) {
    return u == 0 ? v.x : u == 1 ? v.y : u == 2 ? v.z : v.w;
}

// XSEL: 0 = param X, 1 = g_h2.  HHALF: 1 = write fp16 g_hh, 0 = write fp32 g_h16.
template<int IN, int OUT, int NPT, int XSEL, int HHALF, int LAYER>
__global__ void __launch_bounds__(256) lin_kernel(const float* __restrict__ Xp,
                                                  const float* __restrict__ W,
                                                  const float* __restrict__ av,
                                                  const float* __restrict__ adv)
{
    constexpr int TPG    = OUT / 4;        // threads covering one node's channels
    constexpr int GROUPS = 256 / TPG;
    constexpr int NPB    = GROUPS * NPT;   // nodes per block
    __shared__ float4 sw4[IN * OUT / 4];
    __shared__ float4 sx4[NPB * IN / 4];

    const float* X = (XSEL == 0) ? Xp : g_h2;
    const float4* X4 = reinterpret_cast<const float4*>(X);
    const float4* W4 = reinterpret_cast<const float4*>(W);

    int tid = threadIdx.x;
    int node0 = blockIdx.x * NPB;

    for (int i = tid; i < IN * OUT / 4; i += 256) sw4[i] = W4[i];
    for (int i = tid; i < NPB * IN / 4; i += 256) {
        int n = node0 + i / (IN / 4);
        sx4[i] = (n < NN) ? X4[(size_t)n * (IN / 4) + (i % (IN / 4))]
                          : make_float4(0.f, 0.f, 0.f, 0.f);
    }
    __syncthreads();

    int grp = tid / TPG;
    int c4  = (tid % TPG) * 4;

    float acc[NPT][4];
#pragma unroll
    for (int n = 0; n < NPT; n++)
#pragma unroll
        for (int c = 0; c < 4; c++) acc[n][c] = 0.f;

#pragma unroll 4
    for (int k4 = 0; k4 < IN / 4; k4++) {
        float4 xv[NPT];
#pragma unroll
        for (int n = 0; n < NPT; n++)
            xv[n] = sx4[(grp * NPT + n) * (IN / 4) + k4];
#pragma unroll
        for (int u = 0; u < 4; u++) {
            float4 wv = sw4[(k4 * 4 + u) * (OUT / 4) + (c4 >> 2)];
#pragma unroll
            for (int n = 0; n < NPT; n++) {
                float xk = compo(xv[n], u);
                acc[n][0] = fmaf(xk, wv.x, acc[n][0]);
                acc[n][1] = fmaf(xk, wv.y, acc[n][1]);
                acc[n][2] = fmaf(xk, wv.z, acc[n][2]);
                acc[n][3] = fmaf(xk, wv.w, acc[n][3]);
            }
        }
    }

    float4 avv  = *reinterpret_cast<const float4*>(&av[c4]);
    float4 advv = *reinterpret_cast<const float4*>(&adv[c4]);

    float local_mx = -1e30f;
#pragma unroll
    for (int n = 0; n < NPT; n++) {
        int node = node0 + grp * NPT + n;
        if (node < NN) {
            if (HHALF) {
                __half2 ha = __floats2half2_rn(acc[n][0], acc[n][1]);
                __half2 hb = __floats2half2_rn(acc[n][2], acc[n][3]);
                __half2* dst = reinterpret_cast<__half2*>(
                    reinterpret_cast<__half*>(g_hh4) + (size_t)node * 64 + c4);
                dst[0] = ha; dst[1] = hb;
            } else {
                *reinterpret_cast<float4*>(&g_h16[(size_t)node * OUT + c4]) =
                    make_float4(acc[n][0], acc[n][1], acc[n][2], acc[n][3]);
            }
        }

        float vs = acc[n][0] * avv.x + acc[n][1] * avv.y + acc[n][2] * avv.z + acc[n][3] * avv.w;
        float vd = acc[n][0] * advv.x + acc[n][1] * advv.y + acc[n][2] * advv.z + acc[n][3] * advv.w;
#pragma unroll
        for (int off = TPG / 2; off >= 1; off >>= 1) {
            vs += __shfl_xor_sync(0xffffffffu, vs, off);
            vd += __shfl_xor_sync(0xffffffffu, vd, off);
        }
        if ((tid % TPG) == 0 && node < NN) {
            g_asrc[node] = vs;
            g_adst[node] = vd;
            local_mx = fmaxf(local_mx, vs);
        }
    }
#pragma unroll
    for (int off = 16; off >= 1; off >>= 1)
        local_mx = fmaxf(local_mx, __shfl_xor_sync(0xffffffffu, local_mx, off));
    if ((tid & 31) == 0) atomicMaxF(&g_amax[LAYER], local_mx);
}

// ================= single-pass aggregation, C=64 fp16, warp per dst node =================
// 8 lanes per edge (uint4 = 8 half channels), 4 edges per step-group.
template<bool RELU, int LAYER>
__global__ void __launch_bounds__(256) agg64_kernel(const float* __restrict__ b)
{
    __shared__ float2 stage[8][32];
    int w = (blockIdx.x * blockDim.x + threadIdx.x) >> 5;
    int lane = threadIdx.x & 31;
    int wwarp = threadIdx.x >> 5;
    if (w >= NN) return;

    int start = g_rowptr[w], end = g_rowptr[w + 1];
    float adst = g_adst[w];
    float C = fmaxf(adst + g_amax[LAYER], 0.f);   // any shift >= max(e) works

    int grp = lane >> 3;        // which of 4 edges in a chunk
    int q   = lane & 7;         // uint4 index within row (8 channels each)
    float acc[8];
#pragma unroll
    for (int u = 0; u < 8; u++) acc[u] = 0.f;
    float psum = 0.f;

    for (int j0 = start; j0 < end; j0 += 32) {
        int j = j0 + lane;
        float p = 0.f; int s = 0;
        if (j < end) {
            s = (int)g_srcs16[j];
            float t = g_asrc[s] + adst;
            float e = (t > 0.f) ? t : 0.2f * t;
            p = __expf(e - C);
            psum += p;
        }
        stage[wwarp][lane] = make_float2(p, __int_as_float(s));
        __syncwarp();
        int cnt = end - j0;
#pragma unroll
        for (int kb = 0; kb < 32; kb += 8) {
            if (kb < cnt) {
                // two 4-edge groups per chunk for MLP=2 per lane
                float2 psA = stage[wwarp][kb + grp];
                float2 psB = stage[wwarp][kb + 4 + grp];
                uint4 ha = g_hh4[(size_t)__float_as_int(psA.y) * 8 + q];
                uint4 hb = g_hh4[(size_t)__float_as_int(psB.y) * 8 + q];
                float2 f0 = __half22float2(*reinterpret_cast<__half2*>(&ha.x));
                float2 f1 = __half22float2(*reinterpret_cast<__half2*>(&ha.y));
                float2 f2 = __half22float2(*reinterpret_cast<__half2*>(&ha.z));
                float2 f3 = __half22float2(*reinterpret_cast<__half2*>(&ha.w));
                acc[0] = fmaf(psA.x, f0.x, acc[0]); acc[1] = fmaf(psA.x, f0.y, acc[1]);
                acc[2] = fmaf(psA.x, f1.x, acc[2]); acc[3] = fmaf(psA.x, f1.y, acc[3]);
                acc[4] = fmaf(psA.x, f2.x, acc[4]); acc[5] = fmaf(psA.x, f2.y, acc[5]);
                acc[6] = fmaf(psA.x, f3.x, acc[6]); acc[7] = fmaf(psA.x, f3.y, acc[7]);
                f0 = __half22float2(*reinterpret_cast<__half2*>(&hb.x));
                f1 = __half22float2(*reinterpret_cast<__half2*>(&hb.y));
                f2 = __half22float2(*reinterpret_cast<__half2*>(&hb.z));
                f3 = __half22float2(*reinterpret_cast<__half2*>(&hb.w));
                acc[0] = fmaf(psB.x, f0.x, acc[0]); acc[1] = fmaf(psB.x, f0.y, acc[1]);
                acc[2] = fmaf(psB.x, f1.x, acc[2]); acc[3] = fmaf(psB.x, f1.y, acc[3]);
                acc[4] = fmaf(psB.x, f2.x, acc[4]); acc[5] = fmaf(psB.x, f2.y, acc[5]);
                acc[6] = fmaf(psB.x, f3.x, acc[6]); acc[7] = fmaf(psB.x, f3.y, acc[7]);
            }
        }
        __syncwarp();
    }
#pragma unroll
    for (int o = 16; o; o >>= 1) psum += __shfl_xor_sync(0xffffffffu, psum, o);
    // reduce the 4 edge-groups (grp = lane bits 3,4)
#pragma unroll
    for (int o = 8; o <= 16; o <<= 1)
#pragma unroll
        for (int u = 0; u < 8; u++)
            acc[u] += __shfl_xor_sync(0xffffffffu, acc[u], o);

    if (lane < 8) {
        float inv = 1.f / (psum + 1e-16f);
        int ch8 = q * 8;
        float4 b0 = *reinterpret_cast<const float4*>(&b[ch8]);
        float4 b1 = *reinterpret_cast<const float4*>(&b[ch8 + 4]);
        float v0 = acc[0] * inv + b0.x, v1 = acc[1] * inv + b0.y;
        float v2 = acc[2] * inv + b0.z, v3 = acc[3] * inv + b0.w;
        float v4 = acc[4] * inv + b1.x, v5 = acc[5] * inv + b1.y;
        float v6 = acc[6] * inv + b1.z, v7 = acc[7] * inv + b1.w;
        if (RELU) {
            v0 = fmaxf(v0, 0.f); v1 = fmaxf(v1, 0.f); v2 = fmaxf(v2, 0.f); v3 = fmaxf(v3, 0.f);
            v4 = fmaxf(v4, 0.f); v5 = fmaxf(v5, 0.f); v6 = fmaxf(v6, 0.f); v7 = fmaxf(v7, 0.f);
        }
        *reinterpret_cast<float4*>(&g_h2[(size_t)w * 64 + ch8])     = make_float4(v0, v1, v2, v3);
        *reinterpret_cast<float4*>(&g_h2[(size_t)w * 64 + ch8 + 4]) = make_float4(v4, v5, v6, v7);
    }
}

// ================= single-pass aggregation, C=16 fp32, 8 edges/step =================
__global__ void __launch_bounds__(256) agg16_kernel(const float* __restrict__ b,
                                                    float* __restrict__ O)
{
    __shared__ float2 stage[8][32];
    int w = (blockIdx.x * blockDim.x + threadIdx.x) >> 5;
    int lane = threadIdx.x & 31;
    int wwarp = threadIdx.x >> 5;
    if (w >= NN) return;

    int start = g_rowptr[w], end = g_rowptr[w + 1];
    float adst = g_adst[w];
    float C = fmaxf(adst + g_amax[2], 0.f);

    int grp = lane >> 2;        // which of 8 edges
    int ch4 = (lane & 3) * 4;   // channel quad
    float psum = 0.f;
    float ac0 = 0.f, ac1 = 0.f, ac2 = 0.f, ac3 = 0.f;

    for (int j0 = start; j0 < end; j0 += 32) {
        int j = j0 + lane;
        float p = 0.f; int s = 0;
        if (j < end) {
            s = (int)g_srcs16[j];
            float t = g_asrc[s] + adst;
            float e = (t > 0.f) ? t : 0.2f * t;
            p = __expf(e - C);
            psum += p;
        }
        stage[wwarp][lane] = make_float2(p, __int_as_float(s));
        __syncwarp();
        int cnt = end - j0;
#pragma unroll
        for (int kb = 0; kb < 32; kb += 8) {
            if (kb < cnt) {
                float2 ps = stage[wwarp][kb + grp];
                float4 hv = *reinterpret_cast<const float4*>(
                    &g_h16[(size_t)__float_as_int(ps.y) * 16 + ch4]);
                ac0 = fmaf(ps.x, hv.x, ac0);
                ac1 = fmaf(ps.x, hv.y, ac1);
                ac2 = fmaf(ps.x, hv.z, ac2);
                ac3 = fmaf(ps.x, hv.w, ac3);
            }
        }
        __syncwarp();
    }
#pragma unroll
    for (int o = 16; o; o >>= 1) psum += __shfl_xor_sync(0xffffffffu, psum, o);
#pragma unroll
    for (int o = 4; o <= 16; o <<= 1) {
        ac0 += __shfl_xor_sync(0xffffffffu, ac0, o);
        ac1 += __shfl_xor_sync(0xffffffffu, ac1, o);
        ac2 += __shfl_xor_sync(0xffffffffu, ac2, o);
        ac3 += __shfl_xor_sync(0xffffffffu, ac3, o);
    }

    if (lane < 4) {
        float inv = 1.f / (psum + 1e-16f);
        float4 bb = *reinterpret_cast<const float4*>(&b[ch4]);
        *reinterpret_cast<float4*>(&O[(size_t)w * 16 + ch4]) =
            make_float4(ac0 * inv + bb.x, ac1 * inv + bb.y,
                        ac2 * inv + bb.z, ac3 * inv + bb.w);
    }
}

// ================= launch =================
static cudaStream_t g_s2 = 0;
static cudaEvent_t  g_eF = 0, g_eJ = 0;

extern "C" void kernel_launch(void* const* d_in, const int* in_sizes, int n_in,
                              void* d_out, int out_size) {
    const float* x   = (const float*)d_in[0];
    const int*   ei  = (const int*)  d_in[1];
    const float* W1  = (const float*)d_in[3];
    const float* as1 = (const float*)d_in[4];
    const float* ad1 = (const float*)d_in[5];
    const float* b1  = (const float*)d_in[6];
    const float* W2  = (const float*)d_in[7];
    const float* as2 = (const float*)d_in[8];
    const float* ad2 = (const float*)d_in[9];
    const float* b2  = (const float*)d_in[10];
    const float* W3  = (const float*)d_in[11];
    const float* as3 = (const float*)d_in[12];
    const float* ad3 = (const float*)d_in[13];
    const float* b3  = (const float*)d_in[14];
    float* out = (float*)d_out;

    if (!g_s2) {
        cudaStreamCreateWithFlags(&g_s2, cudaStreamNonBlocking);
        cudaEventCreateWithFlags(&g_eF, cudaEventDisableTiming);
        cudaEventCreateWithFlags(&g_eJ, cudaEventDisableTiming);
    }

    // ---- fork: lin1 on side stream, CSR build on main stream ----
    cudaEventRecord(g_eF, 0);
    cudaStreamWaitEvent(g_s2, g_eF, 0);
    lin_kernel<128, 64, 2, 0, 1, 0><<<(NN + 31) / 32, 256, 0, g_s2>>>(x, W1, as1, ad1);
    cudaEventRecord(g_eJ, g_s2);

    zero_cnt_kernel<<<(NN + 255) / 256, 256>>>();
    hist_kernel<<<(EE / 4 + 255) / 256, 256>>>(ei);
    scan_reduce<<<SCAN_B, 256>>>();
    scan_bsums<<<1, 256>>>();
    scan_final<<<SCAN_B, 256>>>();
    scatter_kernel<<<(EE / 4 + 255) / 256, 256>>>(ei);

    cudaStreamWaitEvent(0, g_eJ, 0);   // join lin1 into main stream

    const int AGG_GRID = (NN + 7) / 8;

    agg64_kernel<true, 0><<<AGG_GRID, 256>>>(b1);

    lin_kernel<64, 64, 4, 1, 1, 1><<<(NN + 63) / 64, 256>>>(x, W2, as2, ad2);
    agg64_kernel<true, 1><<<AGG_GRID, 256>>>(b2);

    lin_kernel<64, 16, 2, 1, 0, 2><<<(NN + 127) / 128, 256>>>(x, W3, as3, ad3);
    agg16_kernel<<<AGG_GRID, 256>>>(b3, out);
}